// round 12
// baseline (speedup 1.0000x reference)
#include <cuda_runtime.h>
#include <cuda_bf16.h>

// Problem constants
#define BB 4
#define LL 1024
#define HH 8
#define DD 512
#define DK 64
#define HB 32           // H*B
#define ML 4096         // B*L
#define LOG2E 1.4426950408889634f

// Scratch (allocation-free rule: __device__ globals). Explicit 16B alignment
// for float4 access.
__device__ __align__(16) float g_QP[ML * DD];
__device__ __align__(16) float g_KP[ML * DD];
__device__ __align__(16) float g_VP[ML * DD];
__device__ __align__(16) float g_OH[ML * DD];

// ---------------------------------------------------------------------------
// Double-buffered SGEMM body. BM=128, BK=16, 256 threads.
//   BN=128, TN=8 : split-half 8x8 microtile (rows ty*4 & 64+ty*4,
//                  cols tx*4 & 64+tx*4)  -- conflict-free LDS.128
//   BN=64,  TN=4 : split-half rows, cols tx*4
//   BT=true :  C[M,N] = alpha * A[M,K] * B[N,K]^T   (both K-major, "NT")
//   BT=false:  C[M,N] = alpha * A[M,K] * B[K,N]     ("NN")
// Smem row strides (132 / 68 floats) are multiples of 4 floats => every
// float4 smem access is 16B-aligned (the round-3 fault was stride 130 = 8
// mod 16 bytes).
// Requires: M % 128 == 0, N % BN == 0, K % 16 == 0, pointers 16B-aligned.
// ---------------------------------------------------------------------------
template <int BN, int TN, bool BT>
__device__ __forceinline__ void gemm_big(const float* __restrict__ A, int lda,
                                         const float* __restrict__ Bm, int ldb,
                                         float* __restrict__ C, int ldc,
                                         int K, float alpha)
{
    __shared__ float As[2][16][128 + 4];
    __shared__ float Bs[2][16][BN + 4];

    const int tid = threadIdx.x;
    const int tx  = tid & 15;        // 0..15 column group
    const int ty  = tid >> 4;        // 0..15 row group
    const int m0  = blockIdx.y * 128;
    const int n0  = blockIdx.x * BN;

    // A (and BT-B) loader: one row, 8 consecutive k per thread
    const int arow = tid >> 1;            // 0..127
    const int ak   = (tid & 1) * 8;       // 0 or 8
    // NN-B loader: one k-row, 4 consecutive n per thread
    const int bkr  = tid >> 4;            // 0..15
    const int bnn  = (tid & 15) * 4;      // 0..60

    float4 a0, a1, b0, b1;

    // ---- prologue: load tile 0 into buffer 0 ----
    a0 = *(const float4*)&A[(size_t)(m0 + arow) * lda + ak];
    a1 = *(const float4*)&A[(size_t)(m0 + arow) * lda + ak + 4];
    if (BT) {
        b0 = *(const float4*)&Bm[(size_t)(n0 + arow) * ldb + ak];
        b1 = *(const float4*)&Bm[(size_t)(n0 + arow) * ldb + ak + 4];
    } else {
        b0 = *(const float4*)&Bm[(size_t)bkr * ldb + n0 + bnn];
    }

    As[0][ak + 0][arow] = a0.x;  As[0][ak + 1][arow] = a0.y;
    As[0][ak + 2][arow] = a0.z;  As[0][ak + 3][arow] = a0.w;
    As[0][ak + 4][arow] = a1.x;  As[0][ak + 5][arow] = a1.y;
    As[0][ak + 6][arow] = a1.z;  As[0][ak + 7][arow] = a1.w;
    if (BT) {
        Bs[0][ak + 0][arow] = b0.x;  Bs[0][ak + 1][arow] = b0.y;
        Bs[0][ak + 2][arow] = b0.z;  Bs[0][ak + 3][arow] = b0.w;
        Bs[0][ak + 4][arow] = b1.x;  Bs[0][ak + 5][arow] = b1.y;
        Bs[0][ak + 6][arow] = b1.z;  Bs[0][ak + 7][arow] = b1.w;
    } else {
        *(float4*)&Bs[0][bkr][bnn] = b0;
    }
    __syncthreads();

    float acc[8][TN];
#pragma unroll
    for (int i = 0; i < 8; i++)
#pragma unroll
        for (int j = 0; j < TN; j++) acc[i][j] = 0.0f;

    const int nsteps = K >> 4;
    for (int s = 0; s < nsteps; s++) {
        const int cur = s & 1;
        const int nxt = cur ^ 1;
        const bool has = (s + 1 < nsteps);
        const int kn = (s + 1) << 4;

        if (has) {
            a0 = *(const float4*)&A[(size_t)(m0 + arow) * lda + kn + ak];
            a1 = *(const float4*)&A[(size_t)(m0 + arow) * lda + kn + ak + 4];
            if (BT) {
                b0 = *(const float4*)&Bm[(size_t)(n0 + arow) * ldb + kn + ak];
                b1 = *(const float4*)&Bm[(size_t)(n0 + arow) * ldb + kn + ak + 4];
            } else {
                b0 = *(const float4*)&Bm[(size_t)(kn + bkr) * ldb + n0 + bnn];
            }
        }

#pragma unroll
        for (int kk = 0; kk < 16; kk++) {
            float ar[8], br[TN];
            // rows: ty*4 and 64+ty*4 (broadcast across the 16 tx lanes)
            *(float4*)&ar[0] = *(const float4*)&As[cur][kk][ty * 4];
            *(float4*)&ar[4] = *(const float4*)&As[cur][kk][64 + ty * 4];
            // cols: tx*4 (phase of 8 lanes covers 32 consecutive words ->
            // conflict-free), plus 64+tx*4 for TN==8
            *(float4*)&br[0] = *(const float4*)&Bs[cur][kk][tx * 4];
            if (TN == 8)
                *(float4*)&br[4] = *(const float4*)&Bs[cur][kk][64 + tx * 4];
#pragma unroll
            for (int i = 0; i < 8; i++)
#pragma unroll
                for (int j = 0; j < TN; j++)
                    acc[i][j] = fmaf(ar[i], br[j], acc[i][j]);
        }

        if (has) {
            As[nxt][ak + 0][arow] = a0.x;  As[nxt][ak + 1][arow] = a0.y;
            As[nxt][ak + 2][arow] = a0.z;  As[nxt][ak + 3][arow] = a0.w;
            As[nxt][ak + 4][arow] = a1.x;  As[nxt][ak + 5][arow] = a1.y;
            As[nxt][ak + 6][arow] = a1.z;  As[nxt][ak + 7][arow] = a1.w;
            if (BT) {
                Bs[nxt][ak + 0][arow] = b0.x;  Bs[nxt][ak + 1][arow] = b0.y;
                Bs[nxt][ak + 2][arow] = b0.z;  Bs[nxt][ak + 3][arow] = b0.w;
                Bs[nxt][ak + 4][arow] = b1.x;  Bs[nxt][ak + 5][arow] = b1.y;
                Bs[nxt][ak + 6][arow] = b1.z;  Bs[nxt][ak + 7][arow] = b1.w;
            } else {
                *(float4*)&Bs[nxt][bkr][bnn] = b0;
            }
            __syncthreads();
        }
    }

    // Epilogue: split-half rows (ih) and cols (jh).
#pragma unroll
    for (int ih = 0; ih < 2; ih++) {
#pragma unroll
        for (int i = 0; i < 4; i++) {
            const size_t row =
                (size_t)(m0 + ih * 64 + ty * 4 + i) * ldc + n0;
#pragma unroll
            for (int jh = 0; jh < TN / 4; jh++) {
                float4 o = make_float4(acc[ih * 4 + i][jh * 4 + 0] * alpha,
                                       acc[ih * 4 + i][jh * 4 + 1] * alpha,
                                       acc[ih * 4 + i][jh * 4 + 2] * alpha,
                                       acc[ih * 4 + i][jh * 4 + 3] * alpha);
                *(float4*)&C[row + jh * 64 + tx * 4] = o;
            }
        }
    }
}

// ---------------------------------------------------------------------------
// GEMM wrappers
// ---------------------------------------------------------------------------

// z=0: QP = Q @ Wq^T ; z=1: KP ; z=2: VP.  M=4096,N=512,K=512 (NT)
__global__ void __launch_bounds__(256, 2)
proj_kernel(const float* __restrict__ Q,
            const float* __restrict__ K,
            const float* __restrict__ V,
            const float* __restrict__ Wq,
            const float* __restrict__ Wk,
            const float* __restrict__ Wv)
{
    const float* A;
    const float* W;
    float* C;
    if (blockIdx.z == 0)      { A = Q; W = Wq; C = g_QP; }
    else if (blockIdx.z == 1) { A = K; W = Wk; C = g_KP; }
    else                      { A = V; W = Wv; C = g_VP; }
    gemm_big<128, 8, true>(A, DD, W, DD, C, DD, DD, 1.0f);
}

// scores: per z=h*B+b, S = (Qh Kh^T) / 8   M=N=1024, K=64 (NT)
__global__ void __launch_bounds__(256, 2)
scores_kernel(float* __restrict__ series)
{
    int z = blockIdx.z;
    int h = z >> 2;
    int b = z & 3;
    const float* A  = g_QP + (size_t)b * LL * DD + h * DK;
    const float* Bm = g_KP + (size_t)b * LL * DD + h * DK;
    float* C = series + (size_t)z * LL * LL;
    gemm_big<128, 8, true>(A, DD, Bm, DD, C, LL, DK, 0.125f);
}

// PV: OH[b,i,h*64+d] = sum_m P[z,i,m] * VP[b,m,h*64+d]  M=1024,N=64,K=1024 (NN)
__global__ void __launch_bounds__(256, 2)
pv_kernel(const float* __restrict__ series)
{
    int z = blockIdx.z;
    int h = z >> 2;
    int b = z & 3;
    const float* A  = series + (size_t)z * LL * LL;
    const float* Bm = g_VP + (size_t)b * LL * DD + h * DK;
    float* C = g_OH + (size_t)b * LL * DD + h * DK;
    gemm_big<64, 4, false>(A, LL, Bm, DD, C, DD, LL, 1.0f);
}

// out = OH @ Wo^T   M=4096,N=512,K=512 (NT)
__global__ void __launch_bounds__(256, 2)
outp_kernel(const float* __restrict__ Wo, float* __restrict__ out)
{
    gemm_big<128, 8, true>(g_OH, DD, Wo, DD, out, DD, DD, 1.0f);
}

// ---------------------------------------------------------------------------
// Block reductions (256 threads = 8 warps). Each template instantiation gets
// its own __shared__ red[]; each is called at most once per kernel.
// ---------------------------------------------------------------------------
template <int OP>  // 0 = sum, 1 = max
__device__ __forceinline__ float block_reduce(float v)
{
    __shared__ float red[8];
#pragma unroll
    for (int o = 16; o > 0; o >>= 1) {
        float w = __shfl_xor_sync(0xffffffffu, v, o);
        v = (OP == 1) ? fmaxf(v, w) : (v + w);
    }
    int lane = threadIdx.x & 31;
    int wrp  = threadIdx.x >> 5;
    if (lane == 0) red[wrp] = v;
    __syncthreads();
    float r = red[0];
#pragma unroll
    for (int i = 1; i < 8; i++) r = (OP == 1) ? fmaxf(r, red[i]) : (r + red[i]);
    return r;
}

// ---------------------------------------------------------------------------
// Prior: one block per (h,b,i) row. Fuses the tiny sigma projection.
// The 1/(sqrt(2pi)s) prefactor cancels in the row normalization.
// ---------------------------------------------------------------------------
__global__ void prior_kernel(const float* __restrict__ Sigma,
                             const float* __restrict__ Wsig,
                             float* __restrict__ prior)
{
    int r  = blockIdx.x;          // (h*B+b)*L + i
    int i  = r & (LL - 1);
    int hb = r >> 10;
    int h  = hb >> 2;
    int b  = hb & 3;

    float sig = 0.0f;
#pragma unroll
    for (int k = 0; k < HH; k++)
        sig = fmaf(Sigma[((size_t)(b * LL + i)) * HH + k], Wsig[h * HH + k], sig);

    float t = -LOG2E / (2.0f * sig * sig);   // base-2 exponent coefficient

    int j0 = threadIdx.x * 4;
    float v[4];
    float s = 0.0f;
#pragma unroll
    for (int u = 0; u < 4; u++) {
        float d = (float)(i - (j0 + u));
        v[u] = exp2f(d * d * t);
        s += v[u];
    }
    float tot = block_reduce<0>(s);
    float inv = 1.0f / tot;
    float4 o = make_float4(v[0] * inv, v[1] * inv, v[2] * inv, v[3] * inv);
    *(float4*)&prior[(size_t)r * LL + j0] = o;
}

// ---------------------------------------------------------------------------
// Softmax in-place over the series region (raw scaled scores already there).
// One block (256 threads) per row of 1024.
// ---------------------------------------------------------------------------
__global__ void softmax_kernel(float* __restrict__ series)
{
    size_t base = (size_t)blockIdx.x * LL;
    int j0 = threadIdx.x * 4;
    float4 sv = *(const float4*)&series[base + j0];
    float s[4] = {sv.x, sv.y, sv.z, sv.w};

    float mx = fmaxf(fmaxf(s[0], s[1]), fmaxf(s[2], s[3]));
    mx = block_reduce<1>(mx);

    float e[4];
    float sum = 0.0f;
#pragma unroll
    for (int u = 0; u < 4; u++) {
        e[u] = exp2f((s[u] - mx) * LOG2E);
        sum += e[u];
    }
    __syncthreads();   // order max-phase smem reads before sum-phase writes
    sum = block_reduce<0>(sum);
    float inv = 1.0f / sum;
    float4 o = make_float4(e[0] * inv, e[1] * inv, e[2] * inv, e[3] * inv);
    *(float4*)&series[base + j0] = o;
}

// ---------------------------------------------------------------------------
// Launch.
// d_out layout (tuple order): prior[32*1024*1024] | series[32*1024*1024] |
//                             out[4*1024*512]
// ---------------------------------------------------------------------------
extern "C" void kernel_launch(void* const* d_in, const int* in_sizes, int n_in,
                              void* d_out, int out_size)
{
    const float* Sigma = (const float*)d_in[0];
    const float* Q     = (const float*)d_in[1];
    const float* K     = (const float*)d_in[2];
    const float* V     = (const float*)d_in[3];
    const float* Wsig  = (const float*)d_in[4];
    const float* Wq    = (const float*)d_in[5];
    const float* Wk    = (const float*)d_in[6];
    const float* Wv    = (const float*)d_in[7];
    const float* Wo    = (const float*)d_in[8];

    float* prior  = (float*)d_out;
    float* series = prior + (size_t)HB * LL * LL;
    float* obuf   = series + (size_t)HB * LL * LL;

    // Prior path (independent of attention path)
    prior_kernel<<<HB * LL, 256>>>(Sigma, Wsig, prior);

    // Projections: QP/KP/VP
    proj_kernel<<<dim3(DD / 128, ML / 128, 3), 256>>>(Q, K, V, Wq, Wk, Wv);

    // Attention
    scores_kernel<<<dim3(LL / 128, LL / 128, HB), 256>>>(series);
    softmax_kernel<<<HB * LL, 256>>>(series);
    pv_kernel<<<dim3(DK / 64, LL / 128, HB), 256>>>(series);

    // Output projection
    outp_kernel<<<dim3(DD / 128, ML / 128, 1), 256>>>(Wo, obuf);
}